// round 12
// baseline (speedup 1.0000x reference)
#include <cuda_runtime.h>
#include <cstdint>

#define HD  128
#define BBZ 512
#define LL  1000
#define NB  16
#define CLN 4
#define NTHREADS 512
#define KSTR 130
#define WGST (32 * KSTR)     // gate stride in floats within a weight matrix

#define OFF_W1 0
#define OFF_W2 16640
#define OFF_W3 33280
#define OFF_H1 49920
#define OFF_H2 54016
#define SMEM_FLOATS 58112
#define SMEM_BYTES (SMEM_FLOATS * 4)

typedef unsigned long long u64t;

__device__ __forceinline__ float sigf(float v) {
    return __fdividef(1.f, 1.f + __expf(-v));
}
__device__ __forceinline__ float tanhf_fast(float v) {
    float a = fabsf(v);
    float e = __expf(-2.f * a);
    return copysignf(__fdividef(1.f - e, 1.f + e), v);
}
__device__ __forceinline__ void cluster_bar() {
    asm volatile("barrier.cluster.arrive.aligned;" ::: "memory");
    asm volatile("barrier.cluster.wait.aligned;" ::: "memory");
}
__device__ __forceinline__ void ffma2(u64t& d, u64t a, u64t b) {
    asm("fma.rn.f32x2 %0, %1, %2, %0;" : "+l"(d) : "l"(a), "l"(b));
}
__device__ __forceinline__ float hadd2(u64t d) {
    float lo, hi;
    asm("mov.b64 {%0, %1}, %2;" : "=f"(lo), "=f"(hi) : "l"(d));
    return lo + hi;
}
__device__ __forceinline__ void st_cluster(uint32_t a, float v) {
    asm volatile("st.shared::cluster.f32 [%0], %1;" :: "r"(a), "f"(v) : "memory");
}

__global__ void __launch_bounds__(NTHREADS, 1) __cluster_dims__(CLN, 1, 1)
lstm_persistent_kernel(const float* __restrict__ x,
                       const float* __restrict__ w_ih1,
                       const float* __restrict__ w_hh1,
                       const float* __restrict__ b_ih1,
                       const float* __restrict__ b_hh1,
                       const float* __restrict__ w_ih2,
                       const float* __restrict__ w_hh2,
                       const float* __restrict__ b_ih2,
                       const float* __restrict__ b_hh2,
                       const float* __restrict__ w_lin,
                       const float* __restrict__ b_lin,
                       float* __restrict__ out)
{
    extern __shared__ float sm[];
    const int tid = threadIdx.x;
    uint32_t rank;
    asm("mov.u32 %0, %%cluster_ctarank;" : "=r"(rank));
    const int cid = blockIdx.x / CLN;
    const int batch0 = cid * NB;

    // ---- init: weight slices, layout [gate][unit][k] stride KSTR ----
    for (int idx = tid; idx < 4 * 32 * HD; idx += NTHREADS) {
        int g = idx >> 12, u5 = (idx >> 7) & 31, k = idx & 127;
        int R = g * HD + (int)rank * 32 + u5;
        int o = (g * 32 + u5) * KSTR + k;
        sm[OFF_W1 + o] = w_hh1[R * HD + k];
        sm[OFF_W2 + o] = w_ih2[R * HD + k];
        sm[OFF_W3 + o] = w_hh2[R * HD + k];
    }
    for (int idx = tid; idx < 4096; idx += NTHREADS) {
        sm[OFF_H1 + idx] = 0.f;
        sm[OFF_H2 + idx] = 0.f;
    }

    // warp roles: bg = batch group (4 batches), ks = k-quarter (32 k)
    const int u  = tid & 31;
    const int w  = tid >> 5;           // 0..15
    const int bg = w & 3;
    const int ks = w >> 2;
    const int b0 = bg * 4;
    const int gu = (int)rank * 32 + u;
    const int kbase = ks * 32;
    const int owned = b0 + ks;

    const float wi0 = w_ih1[0 * HD + gu], wi1 = w_ih1[1 * HD + gu];
    const float wi2 = w_ih1[2 * HD + gu], wi3 = w_ih1[3 * HD + gu];
    const float bA0 = b_ih1[0 * HD + gu] + b_hh1[0 * HD + gu];
    const float bA1 = b_ih1[1 * HD + gu] + b_hh1[1 * HD + gu];
    const float bA2 = b_ih1[2 * HD + gu] + b_hh1[2 * HD + gu];
    const float bA3 = b_ih1[3 * HD + gu] + b_hh1[3 * HD + gu];
    const float bB0 = b_ih2[0 * HD + gu] + b_hh2[0 * HD + gu];
    const float bB1 = b_ih2[1 * HD + gu] + b_hh2[1 * HD + gu];
    const float bB2 = b_ih2[2 * HD + gu] + b_hh2[2 * HD + gu];
    const float bB3 = b_ih2[3 * HD + gu] + b_hh2[3 * HD + gu];
    const float wl0 = w_lin[u], wl1 = w_lin[u + 32];
    const float wl2 = w_lin[u + 64], wl3 = w_lin[u + 96];
    const float blin = b_lin[0];

    float c1 = 0.f, c2 = 0.f;

    const uint32_t sbase = (uint32_t)__cvta_generic_to_shared(sm);
    uint32_t peer[CLN];
#pragma unroll
    for (int r = 0; r < CLN; r++)
        asm("mapa.shared::cluster.u32 %0, %1, %2;" : "=r"(peer[r]) : "r"(sbase), "r"(r));

    // per-thread weight base pointers (C-level, 8B-aligned)
    const float* wm1 = sm + OFF_W1 + u * KSTR + kbase;
    const float* wm2 = sm + OFF_W2 + u * KSTR + kbase;
    const float* wm3 = sm + OFF_W3 + u * KSTR + kbase;
    const size_t xrow = (size_t)(batch0 + owned) * LL;

    __syncthreads();
    cluster_bar();

    for (int t = 0; t < LL; ++t) {
        const int pbuf = t & 1, qbuf = pbuf ^ 1;
        const float xv = x[xrow + t];

        // ---------------- layer 1 matvec: Whh1 @ h1[qbuf], k-quarter ----------------
        u64t acc[4][4];
#pragma unroll
        for (int g = 0; g < 4; g++)
#pragma unroll
            for (int b = 0; b < 4; b++) acc[g][b] = 0ULL;
        {
            const ulonglong2* hq =
                (const ulonglong2*)(sm + OFF_H1 + qbuf * 2048 + b0 * 128 + kbase);
#pragma unroll
            for (int i = 0; i < 8; ++i) {
                u64t wp[4][2];
#pragma unroll
                for (int g = 0; g < 4; g++) {
                    const u64t* p = (const u64t*)(wm1 + g * WGST) + 2 * i;
                    wp[g][0] = p[0]; wp[g][1] = p[1];
                }
#pragma unroll
                for (int b = 0; b < 4; b++) {
                    ulonglong2 hv = hq[b * 32 + i];
#pragma unroll
                    for (int g = 0; g < 4; g++) {
                        ffma2(acc[g][b], wp[g][0], hv.x);
                        ffma2(acc[g][b], wp[g][1], hv.y);
                    }
                }
            }
        }
        // ---- 4-way k-reduction: 2 rounds via dead h regions (C-level, fenced) ----
        float s[4][4];
#pragma unroll
        for (int g = 0; g < 4; g++)
#pragma unroll
            for (int b = 0; b < 4; b++) s[g][b] = hadd2(acc[g][b]);
        {
            float* scrA = sm + OFF_H1 + qbuf * 2048;     // dead: h1 from t-1, already read
            float* scrB = sm + OFF_H2 + pbuf * 2048;     // dead: h2 from t-2
            float* myscr = (w < 8) ? scrA : scrB;
            __syncthreads();                             // matvec reads of h1[qbuf] done
#pragma unroll
            for (int j = 0; j < 2; j++) {
                const int bl = ((ks & 1) ^ 1) + 2 * j;   // send non-kept batches
#pragma unroll
                for (int g = 0; g < 4; g++)
                    myscr[((((w & 7) * 2 + j) * 4 + g) * 32) + u] = s[g][bl];
            }
            __syncthreads();
#pragma unroll
            for (int j = 0; j < 2; j++) {
                const int bl = (ks & 1) + 2 * j;         // gather kept batches
#pragma unroll
                for (int g = 0; g < 4; g++)
                    s[g][bl] += myscr[(((((w ^ 4) & 7) * 2 + j) * 4 + g) * 32) + u];
            }
            __syncthreads();
#pragma unroll
            for (int g = 0; g < 4; g++)                  // round 2: send partner's batch
                scrA[((w * 4 + g) * 32) + u] = s[g][ks ^ 2];
            __syncthreads();
#pragma unroll
            for (int g = 0; g < 4; g++)
                s[g][ks] += scrA[(((w ^ 8) * 4 + g) * 32) + u];
        }
        // ---- layer-1 cell (owned batch) + cluster broadcast ----
        {
            float pi = fmaf(xv, wi0, s[0][ks]) + bA0;
            float pf = fmaf(xv, wi1, s[1][ks]) + bA1;
            float pg = fmaf(xv, wi2, s[2][ks]) + bA2;
            float po = fmaf(xv, wi3, s[3][ks]) + bA3;
            float ig = sigf(pi), fg = sigf(pf), gg = tanhf_fast(pg), og = sigf(po);
            float c = fmaf(fg, c1, ig * gg);
            c1 = c;
            float h = og * tanhf_fast(c);
            const uint32_t off = (uint32_t)((OFF_H1 + (pbuf * NB + owned) * 128 + gu) * 4);
#pragma unroll
            for (int r = 0; r < CLN; r++) st_cluster(peer[r] + off, h);
        }
        cluster_bar();

        // ------------- layer 2 matvec: Wih2@h1[pbuf] + Whh2@h2[qbuf] -------------
#pragma unroll
        for (int g = 0; g < 4; g++)
#pragma unroll
            for (int b = 0; b < 4; b++) acc[g][b] = 0ULL;
        {
            const ulonglong2* h1p =
                (const ulonglong2*)(sm + OFF_H1 + pbuf * 2048 + b0 * 128 + kbase);
            const ulonglong2* h2q =
                (const ulonglong2*)(sm + OFF_H2 + qbuf * 2048 + b0 * 128 + kbase);
#pragma unroll
            for (int i = 0; i < 8; ++i) {
                u64t wp2[4][2], wp3[4][2];
#pragma unroll
                for (int g = 0; g < 4; g++) {
                    const u64t* p2 = (const u64t*)(wm2 + g * WGST) + 2 * i;
                    const u64t* p3 = (const u64t*)(wm3 + g * WGST) + 2 * i;
                    wp2[g][0] = p2[0]; wp2[g][1] = p2[1];
                    wp3[g][0] = p3[0]; wp3[g][1] = p3[1];
                }
#pragma unroll
                for (int b = 0; b < 4; b++) {
                    ulonglong2 pv = h1p[b * 32 + i];
                    ulonglong2 qv = h2q[b * 32 + i];
#pragma unroll
                    for (int g = 0; g < 4; g++) {
                        ffma2(acc[g][b], wp2[g][0], pv.x);
                        ffma2(acc[g][b], wp2[g][1], pv.y);
                        ffma2(acc[g][b], wp3[g][0], qv.x);
                        ffma2(acc[g][b], wp3[g][1], qv.y);
                    }
                }
            }
        }
        // ---- reduction (scratch: h1[qbuf] trashed above; h2[qbuf] dead post-matvec) ----
#pragma unroll
        for (int g = 0; g < 4; g++)
#pragma unroll
            for (int b = 0; b < 4; b++) s[g][b] = hadd2(acc[g][b]);
        {
            float* scrA = sm + OFF_H1 + qbuf * 2048;
            float* scrB = sm + OFF_H2 + qbuf * 2048;
            float* myscr = (w < 8) ? scrA : scrB;
            __syncthreads();                             // matvec reads done
#pragma unroll
            for (int j = 0; j < 2; j++) {
                const int bl = ((ks & 1) ^ 1) + 2 * j;
#pragma unroll
                for (int g = 0; g < 4; g++)
                    myscr[((((w & 7) * 2 + j) * 4 + g) * 32) + u] = s[g][bl];
            }
            __syncthreads();
#pragma unroll
            for (int j = 0; j < 2; j++) {
                const int bl = (ks & 1) + 2 * j;
#pragma unroll
                for (int g = 0; g < 4; g++)
                    s[g][bl] += myscr[(((((w ^ 4) & 7) * 2 + j) * 4 + g) * 32) + u];
            }
            __syncthreads();
#pragma unroll
            for (int g = 0; g < 4; g++)
                scrA[((w * 4 + g) * 32) + u] = s[g][ks ^ 2];
            __syncthreads();
#pragma unroll
            for (int g = 0; g < 4; g++)
                s[g][ks] += scrA[(((w ^ 8) * 4 + g) * 32) + u];
        }
        // ---- layer-2 cell + broadcast ----
        {
            float pi = s[0][ks] + bB0;
            float pf = s[1][ks] + bB1;
            float pg = s[2][ks] + bB2;
            float po = s[3][ks] + bB3;
            float ig = sigf(pi), fg = sigf(pf), gg = tanhf_fast(pg), og = sigf(po);
            float c = fmaf(fg, c2, ig * gg);
            c2 = c;
            float h = og * tanhf_fast(c);
            const uint32_t off = (uint32_t)((OFF_H2 + (pbuf * NB + owned) * 128 + gu) * 4);
#pragma unroll
            for (int r = 0; r < CLN; r++) st_cluster(peer[r] + off, h);
        }
        cluster_bar();

        // ---- output head: each warp emits its owned batch ----
        {
            const float* hp = sm + OFF_H2 + pbuf * 2048 + owned * 128;
            float d = hp[u] * wl0 + hp[u + 32] * wl1 + hp[u + 64] * wl2 + hp[u + 96] * wl3;
#pragma unroll
            for (int m = 16; m >= 1; m >>= 1)
                d += __shfl_xor_sync(0xffffffffu, d, m);
            if (u == 0) out[xrow + t] = d + blin;
        }
    }
}

extern "C" void kernel_launch(void* const* d_in, const int* in_sizes, int n_in,
                              void* d_out, int out_size)
{
    (void)in_sizes; (void)n_in; (void)out_size;
    cudaFuncSetAttribute(lstm_persistent_kernel,
                         cudaFuncAttributeMaxDynamicSharedMemorySize, SMEM_BYTES);
    lstm_persistent_kernel<<<(BBZ / NB) * CLN, NTHREADS, SMEM_BYTES>>>(
        (const float*)d_in[0], (const float*)d_in[1], (const float*)d_in[2],
        (const float*)d_in[3], (const float*)d_in[4], (const float*)d_in[5],
        (const float*)d_in[6], (const float*)d_in[7], (const float*)d_in[8],
        (const float*)d_in[9], (const float*)d_in[10], (float*)d_out);
}